// round 2
// baseline (speedup 1.0000x reference)
#include <cuda_runtime.h>
#include <cstdint>

// Problem constants
#define BATCH 8
#define TT    4096      // total tokens per batch
#define DIM   512       // input dim
#define NH    8         // heads
#define HD    64        // head dim
#define QDIM  512       // query tokens per batch
#define GG    3584      // kv tokens per batch
#define NORM  0.125f    // 1/sqrt(64)

// Scratch (device globals: allowed; no runtime allocation)
__device__ float g_Q[(size_t)NH*BATCH*QDIM*HD];   // [h][b][q][d]
__device__ float g_K[(size_t)NH*BATCH*GG*HD];     // [h][b][g][d]
__device__ float g_V[(size_t)NH*BATCH*GG*HD];     // [h][b][g][d]
__device__ float g_Hd[(size_t)BATCH*QDIM*NH*HD];  // [b][q][h*64+d]

__device__ __forceinline__ float tfr(float x) {
    uint32_t u; asm("cvt.rna.tf32.f32 %0, %1;" : "=r"(u) : "f"(x));
    return __uint_as_float(u);
}
__device__ __forceinline__ void split(float v, float& hi, float& lo) {
    hi = tfr(v);
    lo = tfr(v - hi);
}

// D(16x8,f32) += A(16x8,tf32) * B(8x8,tf32)
__device__ __forceinline__ void mma8(float* c, const uint32_t* a, const uint32_t* b) {
    asm volatile(
        "mma.sync.aligned.m16n8k8.row.col.f32.tf32.tf32.f32 "
        "{%0,%1,%2,%3},{%4,%5,%6,%7},{%8,%9},{%0,%1,%2,%3};"
        : "+f"(c[0]), "+f"(c[1]), "+f"(c[2]), "+f"(c[3])
        : "r"(a[0]), "r"(a[1]), "r"(a[2]), "r"(a[3]), "r"(b[0]), "r"(b[1]));
}
// 3xTF32: c += (ah+al)*(bh+bl) dropping al*bl  -> ~fp32 accuracy
__device__ __forceinline__ void mma3(float* c, const uint32_t* ah, const uint32_t* al,
                                     const uint32_t* bh, const uint32_t* bl) {
    mma8(c, ah, bl);
    mma8(c, al, bh);
    mma8(c, ah, bh);
}

// ===========================================================================
// Projection GEMM (3xTF32): C(M,N=512) = A(M,512) @ B(512,512)
// MODE 0: Q proj   MODE 1: K proj   MODE 2: V proj   MODE 3: out proj
// Block tile 128x64, K-step 16, 8 warps (4 in M x 2 in N), warp tile 32x32.
// ===========================================================================
template<int MODE>
__global__ __launch_bounds__(256)
void gemm_kernel(const float* __restrict__ X, const float* __restrict__ W,
                 float* __restrict__ Outp)
{
    __shared__ float Ah[128][20], Al[128][20];  // stride 20: r*20%32 distinct mult-of-4
    __shared__ float Bh[16][72],  Bl[16][72];   // stride 72 == 8 mod 32

    const int tid  = threadIdx.x;
    const int lane = tid & 31;
    const int warp = tid >> 5;
    const int wm   = warp >> 1;    // 0..3
    const int wn   = warp & 1;     // 0..1
    const int bm   = blockIdx.y;
    const int bn   = blockIdx.x;   // 0..7 (N/64); for modes 0-2 this IS the head

    const float* Aptr;
    if (MODE == 3) {
        Aptr = g_Hd + (size_t)bm * 128 * 512;
    } else {
        const int RPB = (MODE == 0) ? QDIM : GG;   // rows per batch (tile-aligned)
        const int off = (MODE == 0) ? 0 : QDIM;
        const int rowbase = bm * 128;
        const int bidx  = rowbase / RPB;
        const int tbase = rowbase % RPB + off;
        Aptr = X + ((size_t)bidx * TT + tbase) * DIM;
    }
    const float* Wbase;
    int ldw;
    if (MODE == 3) { Wbase = W + bn * 64;               ldw = 512; }
    else           { Wbase = W + (size_t)bn * DIM * HD; ldw = 64;  }

    float acc[2][4][4];
    #pragma unroll
    for (int a = 0; a < 2; a++)
        #pragma unroll
        for (int b = 0; b < 4; b++)
            #pragma unroll
            for (int c = 0; c < 4; c++) acc[a][b][c] = 0.f;

    for (int k0 = 0; k0 < DIM; k0 += 16) {
        // Load A tile 128x16 (split hi/lo): 512 float4, 2 per thread
        #pragma unroll
        for (int j = 0; j < 2; j++) {
            int idx = tid + j * 256;
            int r = idx >> 2, c4 = idx & 3;
            float4 v = *reinterpret_cast<const float4*>(Aptr + (size_t)r * DIM + k0 + c4 * 4);
            float4 h, l;
            split(v.x, h.x, l.x); split(v.y, h.y, l.y);
            split(v.z, h.z, l.z); split(v.w, h.w, l.w);
            *reinterpret_cast<float4*>(&Ah[r][c4 * 4]) = h;
            *reinterpret_cast<float4*>(&Al[r][c4 * 4]) = l;
        }
        // Load B tile 16x64: 256 float4, 1 per thread
        {
            int r = tid >> 4, c4 = tid & 15;
            float4 v = *reinterpret_cast<const float4*>(Wbase + (size_t)(k0 + r) * ldw + c4 * 4);
            float4 h, l;
            split(v.x, h.x, l.x); split(v.y, h.y, l.y);
            split(v.z, h.z, l.z); split(v.w, h.w, l.w);
            *reinterpret_cast<float4*>(&Bh[r][c4 * 4]) = h;
            *reinterpret_cast<float4*>(&Bl[r][c4 * 4]) = l;
        }
        __syncthreads();

        #pragma unroll
        for (int kk = 0; kk < 2; kk++) {
            uint32_t afh[2][4], afl[2][4];
            #pragma unroll
            for (int mt = 0; mt < 2; mt++) {
                int r0 = wm * 32 + mt * 16 + (lane >> 2);
                int cc = kk * 8 + (lane & 3);
                afh[mt][0] = __float_as_uint(Ah[r0][cc]);
                afh[mt][1] = __float_as_uint(Ah[r0 + 8][cc]);
                afh[mt][2] = __float_as_uint(Ah[r0][cc + 4]);
                afh[mt][3] = __float_as_uint(Ah[r0 + 8][cc + 4]);
                afl[mt][0] = __float_as_uint(Al[r0][cc]);
                afl[mt][1] = __float_as_uint(Al[r0 + 8][cc]);
                afl[mt][2] = __float_as_uint(Al[r0][cc + 4]);
                afl[mt][3] = __float_as_uint(Al[r0 + 8][cc + 4]);
            }
            uint32_t bfh[4][2], bfl[4][2];
            #pragma unroll
            for (int nt = 0; nt < 4; nt++) {
                int cc = wn * 32 + nt * 8 + (lane >> 2);
                int rr = kk * 8 + (lane & 3);
                bfh[nt][0] = __float_as_uint(Bh[rr][cc]);
                bfh[nt][1] = __float_as_uint(Bh[rr + 4][cc]);
                bfl[nt][0] = __float_as_uint(Bl[rr][cc]);
                bfl[nt][1] = __float_as_uint(Bl[rr + 4][cc]);
            }
            #pragma unroll
            for (int mt = 0; mt < 2; mt++)
                #pragma unroll
                for (int nt = 0; nt < 4; nt++)
                    mma3(acc[mt][nt], afh[mt], afl[mt], bfh[nt], bfl[nt]);
        }
        __syncthreads();
    }

    // Epilogue: scatter per-mode
    #pragma unroll
    for (int mt = 0; mt < 2; mt++)
        #pragma unroll
        for (int nt = 0; nt < 4; nt++)
            #pragma unroll
            for (int i = 0; i < 4; i++) {
                int m = bm * 128 + wm * 32 + mt * 16 + (lane >> 2) + ((i & 2) ? 8 : 0);
                int n = bn * 64 + wn * 32 + nt * 8 + 2 * (lane & 3) + (i & 1);
                float v = acc[mt][nt][i];
                if (MODE == 0) {
                    int b = m >> 9, q = m & 511, h = n >> 6, d = n & 63;
                    g_Q[(((size_t)(h * BATCH + b)) * QDIM + q) * HD + d] = v;
                } else if (MODE == 1 || MODE == 2) {
                    int b = m / GG, g = m % GG, h = n >> 6, d = n & 63;
                    size_t o = (((size_t)(h * BATCH + b)) * GG + g) * HD + d;
                    if (MODE == 1) g_K[o] = v; else g_V[o] = v;
                } else {
                    Outp[(size_t)m * 512 + n] = v;
                }
            }
}

// ===========================================================================
// Flash attention (3xTF32): block = (128 q-rows) x (head,batch pair)
// 8 warps, each owns 16 q-rows; Q hi/lo fragments in registers for the whole
// kernel. K/V streamed in 32-row chunks (hi/lo) via SMEM; online softmax;
// P transposed C-layout -> A-layout with warp shuffles, then hi/lo split.
// ===========================================================================
__global__ __launch_bounds__(256)
void attn_kernel()
{
    __shared__ float Kh[32][68], Kl[32][68];   // stride 68 == 4 mod 32
    __shared__ float Vh[32][72], Vl[32][72];   // stride 72 == 8 mod 32

    const int tid  = threadIdx.x;
    const int lane = tid & 31;
    const int warp = tid >> 5;
    const int qt   = blockIdx.x;   // 0..3
    const int pair = blockIdx.y;   // 0..63 == h*8+b

    const float* Qp = g_Q + ((size_t)pair * QDIM + qt * 128 + warp * 16) * HD;
    const float* Kp = g_K + (size_t)pair * GG * HD;
    const float* Vp = g_V + (size_t)pair * GG * HD;

    // Q A-fragments (hi/lo) for all 8 k-steps (d=64), loaded once
    uint32_t qh[8][4], ql[8][4];
    #pragma unroll
    for (int kk = 0; kk < 8; kk++) {
        int r0 = lane >> 2;
        int cc = kk * 8 + (lane & 3);
        float v, h, l;
        v = Qp[(size_t)r0 * HD + cc];            split(v, h, l);
        qh[kk][0] = __float_as_uint(h); ql[kk][0] = __float_as_uint(l);
        v = Qp[(size_t)(r0 + 8) * HD + cc];      split(v, h, l);
        qh[kk][1] = __float_as_uint(h); ql[kk][1] = __float_as_uint(l);
        v = Qp[(size_t)r0 * HD + cc + 4];        split(v, h, l);
        qh[kk][2] = __float_as_uint(h); ql[kk][2] = __float_as_uint(l);
        v = Qp[(size_t)(r0 + 8) * HD + cc + 4];  split(v, h, l);
        qh[kk][3] = __float_as_uint(h); ql[kk][3] = __float_as_uint(l);
    }

    float oacc[8][4];
    #pragma unroll
    for (int t = 0; t < 8; t++)
        #pragma unroll
        for (int i = 0; i < 4; i++) oacc[t][i] = 0.f;
    float m0 = -1e30f, m1 = -1e30f, l0 = 0.f, l1 = 0.f;

    // shuffle sources for C->A fragment transpose (within 4-lane row group)
    const int srcA = (lane & ~3) | ((lane & 3) >> 1);
    const int srcB = srcA + 2;
    const bool odd = lane & 1;

    for (int c = 0; c < GG / 32; c++) {
        __syncthreads();
        // Load K/V chunk (32 x 64), hi/lo split at store: 512 float4 each
        #pragma unroll
        for (int j = 0; j < 2; j++) {
            int idx = tid + j * 256;
            int r = idx >> 4, c4 = idx & 15;
            size_t go = ((size_t)(c * 32 + r)) * HD + c4 * 4;
            float4 v = *reinterpret_cast<const float4*>(Kp + go);
            float4 h, l;
            split(v.x, h.x, l.x); split(v.y, h.y, l.y);
            split(v.z, h.z, l.z); split(v.w, h.w, l.w);
            *reinterpret_cast<float4*>(&Kh[r][c4 * 4]) = h;
            *reinterpret_cast<float4*>(&Kl[r][c4 * 4]) = l;
            float4 v2 = *reinterpret_cast<const float4*>(Vp + go);
            split(v2.x, h.x, l.x); split(v2.y, h.y, l.y);
            split(v2.z, h.z, l.z); split(v2.w, h.w, l.w);
            *reinterpret_cast<float4*>(&Vh[r][c4 * 4]) = h;
            *reinterpret_cast<float4*>(&Vl[r][c4 * 4]) = l;
        }
        __syncthreads();

        // S = Q @ K^T  (16 x 32 per warp)
        float sacc[4][4];
        #pragma unroll
        for (int t = 0; t < 4; t++)
            #pragma unroll
            for (int i = 0; i < 4; i++) sacc[t][i] = 0.f;

        #pragma unroll
        for (int kk = 0; kk < 8; kk++) {
            #pragma unroll
            for (int nt = 0; nt < 4; nt++) {
                uint32_t bh[2], bl[2];
                int gcol = nt * 8 + (lane >> 2);
                int dd   = kk * 8 + (lane & 3);
                bh[0] = __float_as_uint(Kh[gcol][dd]);
                bh[1] = __float_as_uint(Kh[gcol][dd + 4]);
                bl[0] = __float_as_uint(Kl[gcol][dd]);
                bl[1] = __float_as_uint(Kl[gcol][dd + 4]);
                mma3(sacc[nt], qh[kk], ql[kk], bh, bl);
            }
        }

        // Online softmax (rows r0 = lane>>2 and r0+8 within warp band)
        float mx0 = -1e30f, mx1 = -1e30f;
        #pragma unroll
        for (int t = 0; t < 4; t++) {
            sacc[t][0] *= NORM; sacc[t][1] *= NORM;
            sacc[t][2] *= NORM; sacc[t][3] *= NORM;
            mx0 = fmaxf(mx0, fmaxf(sacc[t][0], sacc[t][1]));
            mx1 = fmaxf(mx1, fmaxf(sacc[t][2], sacc[t][3]));
        }
        mx0 = fmaxf(mx0, __shfl_xor_sync(0xffffffffu, mx0, 1));
        mx0 = fmaxf(mx0, __shfl_xor_sync(0xffffffffu, mx0, 2));
        mx1 = fmaxf(mx1, __shfl_xor_sync(0xffffffffu, mx1, 1));
        mx1 = fmaxf(mx1, __shfl_xor_sync(0xffffffffu, mx1, 2));

        float mn0 = fmaxf(m0, mx0), mn1 = fmaxf(m1, mx1);
        float al0 = __expf(m0 - mn0), al1 = __expf(m1 - mn1);
        float s0 = 0.f, s1 = 0.f;
        #pragma unroll
        for (int t = 0; t < 4; t++) {
            sacc[t][0] = __expf(sacc[t][0] - mn0);
            sacc[t][1] = __expf(sacc[t][1] - mn0);
            sacc[t][2] = __expf(sacc[t][2] - mn1);
            sacc[t][3] = __expf(sacc[t][3] - mn1);
            s0 += sacc[t][0] + sacc[t][1];
            s1 += sacc[t][2] + sacc[t][3];
        }
        s0 += __shfl_xor_sync(0xffffffffu, s0, 1);
        s0 += __shfl_xor_sync(0xffffffffu, s0, 2);
        s1 += __shfl_xor_sync(0xffffffffu, s1, 1);
        s1 += __shfl_xor_sync(0xffffffffu, s1, 2);
        l0 = l0 * al0 + s0;
        l1 = l1 * al1 + s1;
        m0 = mn0; m1 = mn1;
        #pragma unroll
        for (int nt = 0; nt < 8; nt++) {
            oacc[nt][0] *= al0; oacc[nt][1] *= al0;
            oacc[nt][2] *= al1; oacc[nt][3] *= al1;
        }

        // O += P @ V : transpose P via shuffles, hi/lo split, then mma
        #pragma unroll
        for (int kk = 0; kk < 4; kk++) {
            float t0 = __shfl_sync(0xffffffffu, sacc[kk][0], srcA);
            float t1 = __shfl_sync(0xffffffffu, sacc[kk][1], srcA);
            float t2 = __shfl_sync(0xffffffffu, sacc[kk][2], srcA);
            float t3 = __shfl_sync(0xffffffffu, sacc[kk][3], srcA);
            float u0 = __shfl_sync(0xffffffffu, sacc[kk][0], srcB);
            float u1 = __shfl_sync(0xffffffffu, sacc[kk][1], srcB);
            float u2 = __shfl_sync(0xffffffffu, sacc[kk][2], srcB);
            float u3 = __shfl_sync(0xffffffffu, sacc[kk][3], srcB);
            float p0 = odd ? t1 : t0;
            float p1 = odd ? t3 : t2;
            float p2 = odd ? u1 : u0;
            float p3 = odd ? u3 : u2;
            uint32_t pah[4], pal[4];
            float h, l;
            split(p0, h, l); pah[0] = __float_as_uint(h); pal[0] = __float_as_uint(l);
            split(p1, h, l); pah[1] = __float_as_uint(h); pal[1] = __float_as_uint(l);
            split(p2, h, l); pah[2] = __float_as_uint(h); pal[2] = __float_as_uint(l);
            split(p3, h, l); pah[3] = __float_as_uint(h); pal[3] = __float_as_uint(l);
            #pragma unroll
            for (int nt = 0; nt < 8; nt++) {
                uint32_t bh[2], bl[2];
                int gg2 = kk * 8 + (lane & 3);
                int dd  = nt * 8 + (lane >> 2);
                bh[0] = __float_as_uint(Vh[gg2][dd]);
                bh[1] = __float_as_uint(Vh[gg2 + 4][dd]);
                bl[0] = __float_as_uint(Vl[gg2][dd]);
                bl[1] = __float_as_uint(Vl[gg2 + 4][dd]);
                mma3(oacc[nt], pah, pal, bh, bl);
            }
        }
    }

    // Normalize and write heads to (b, q, h*64+d)
    float inv0 = 1.f / l0, inv1 = 1.f / l1;
    int h = pair >> 3, b = pair & 7;
    #pragma unroll
    for (int nt = 0; nt < 8; nt++)
        #pragma unroll
        for (int i = 0; i < 4; i++) {
            int q = qt * 128 + warp * 16 + (lane >> 2) + ((i & 2) ? 8 : 0);
            int d = nt * 8 + 2 * (lane & 3) + (i & 1);
            float v = oacc[nt][i] * ((i & 2) ? inv1 : inv0);
            g_Hd[((size_t)(b * QDIM + q)) * 512 + h * HD + d] = v;
        }
}

extern "C" void kernel_launch(void* const* d_in, const int* in_sizes, int n_in,
                              void* d_out, int out_size)
{
    (void)in_sizes; (void)n_in; (void)out_size;
    const float* q  = (const float*)d_in[0];
    const float* Wq = (const float*)d_in[1];
    const float* Wk = (const float*)d_in[2];
    const float* Wv = (const float*)d_in[3];
    const float* Wo = (const float*)d_in[4];
    float* out = (float*)d_out;

    gemm_kernel<0><<<dim3(8, 32), 256>>>(q, Wq, nullptr);     // Q proj
    gemm_kernel<1><<<dim3(8, 224), 256>>>(q, Wk, nullptr);    // K proj
    gemm_kernel<2><<<dim3(8, 224), 256>>>(q, Wv, nullptr);    // V proj
    attn_kernel<<<dim3(4, 64), 256>>>();                      // flash attention
    gemm_kernel<3><<<dim3(8, 32), 256>>>(nullptr, Wo, out);   // out proj
}

// round 3
// speedup vs baseline: 1.4998x; 1.4998x over previous
#include <cuda_runtime.h>
#include <cuda_fp16.h>
#include <cstdint>

// Problem constants
#define BATCH 8
#define TT    4096
#define DIM   512
#define NH    8
#define HD    64
#define QDIM  512
#define GG    3584
#define NORM  0.125f
#define NCHUNK 56          // GG / 64

// Packed hi/lo fp16 scratch (u32 = hi in bits[15:0], lo in bits[31:16])
__device__ __align__(256) uint32_t g_Q[(size_t)NH*BATCH*QDIM*HD];
__device__ __align__(256) uint32_t g_K[(size_t)NH*BATCH*GG*HD];
__device__ __align__(256) uint32_t g_V[(size_t)NH*BATCH*GG*HD];
__device__ __align__(256) uint32_t g_Hd[(size_t)BATCH*QDIM*NH*HD];

__device__ __forceinline__ uint32_t packsplit(float v) {
    __half h = __float2half_rn(v);
    __half l = __float2half_rn(v - __half2float(h));
    return (uint32_t)__half_as_ushort(h) | ((uint32_t)__half_as_ushort(l) << 16);
}
// split a pair (p0 -> low/even-k, p1 -> high/odd-k) into hi-pair and lo-pair regs
__device__ __forceinline__ void psplit2(float p0, float p1, uint32_t& hi, uint32_t& lo) {
    __half2 h = __floats2half2_rn(p0, p1);
    float2 hf = __half22float2(h);
    __half2 l = __floats2half2_rn(p0 - hf.x, p1 - hf.y);
    hi = *reinterpret_cast<uint32_t*>(&h);
    lo = *reinterpret_cast<uint32_t*>(&l);
}
#define HI_PAIR(v0, v1) __byte_perm((v0), (v1), 0x5410)
#define LO_PAIR(v0, v1) __byte_perm((v0), (v1), 0x7632)

// D(16x8,f32) += A(16x16,f16) * B(16x8,f16)
__device__ __forceinline__ void mma16(float* c, const uint32_t* a, const uint32_t* b) {
    asm volatile(
        "mma.sync.aligned.m16n8k16.row.col.f32.f16.f16.f32 "
        "{%0,%1,%2,%3},{%4,%5,%6,%7},{%8,%9},{%0,%1,%2,%3};"
        : "+f"(c[0]), "+f"(c[1]), "+f"(c[2]), "+f"(c[3])
        : "r"(a[0]), "r"(a[1]), "r"(a[2]), "r"(a[3]), "r"(b[0]), "r"(b[1]));
}
__device__ __forceinline__ void mma3(float* c, const uint32_t* ah, const uint32_t* al,
                                     const uint32_t* bh, const uint32_t* bl) {
    mma16(c, ah, bl);
    mma16(c, al, bh);
    mma16(c, ah, bh);
}

__device__ __forceinline__ void cpa16(uint32_t dst, const void* src) {
    asm volatile("cp.async.cg.shared.global [%0], [%1], 16;" :: "r"(dst), "l"(src));
}

// ===========================================================================
// Projection GEMMs (fp16 2-term): C(M,N) = A(M,512) @ B(512,N)
// MODE 0: Q proj (out g_Q packed)   MODE 1: K+V proj fused (g_K, g_V packed)
// MODE 2: out proj (A = g_Hd packed, out f32)
// Block tile 128 x 64(per weight), K-step 32, 8 warps (4M x 2N), warp 32x32.
// ===========================================================================
template<int MODE>
__global__ __launch_bounds__(256)
void gemm_kernel(const float* __restrict__ X, const float* __restrict__ W0,
                 const float* __restrict__ W1, float* __restrict__ Outp)
{
    constexpr int NW = (MODE == 1) ? 2 : 1;
    __shared__ uint32_t As[128][40];       // packed hilo, ld40: 8r+2j distinct banks
    __shared__ uint32_t Bs[2][32][68];     // packed hilo, ld68: 8j+n distinct banks

    const int tid  = threadIdx.x;
    const int lane = tid & 31;
    const int warp = tid >> 5;
    const int wm   = warp >> 1;
    const int wn   = warp & 1;
    const int bm   = blockIdx.y;
    const int bn   = blockIdx.x;   // head (MODE 0/1) or N-tile (MODE 2)

    const float* Aptr = nullptr;
    const uint32_t* ApU = nullptr;
    int bidx = 0, t0 = 0;
    if (MODE == 2) {
        ApU = g_Hd + (size_t)bm * 128 * 512;
    } else {
        const int RPB = (MODE == 0) ? QDIM : GG;
        const int off = (MODE == 0) ? 0 : QDIM;
        bidx = (bm * 128) / RPB;
        t0   = (bm * 128) % RPB;
        Aptr = X + ((size_t)bidx * TT + t0 + off) * DIM;
    }
    const int ldw = (MODE == 2) ? 512 : 64;
    const float* Wb0 = (MODE == 2) ? (W0 + bn * 64) : (W0 + (size_t)bn * DIM * HD);
    const float* Wb1 = (MODE == 1) ? (W1 + (size_t)bn * DIM * HD) : nullptr;

    float acc[NW][2][4][4];
    #pragma unroll
    for (int w = 0; w < NW; w++)
        #pragma unroll
        for (int a = 0; a < 2; a++)
            #pragma unroll
            for (int b = 0; b < 4; b++)
                #pragma unroll
                for (int c = 0; c < 4; c++) acc[w][a][b][c] = 0.f;

    for (int k0 = 0; k0 < DIM; k0 += 32) {
        // A tile 128x32 -> packed hilo
        #pragma unroll
        for (int j = 0; j < 4; j++) {
            int idx = tid + j * 256;
            int r = idx >> 3, c4 = idx & 7;
            uint4 p;
            if (MODE == 2) {
                p = *reinterpret_cast<const uint4*>(ApU + (size_t)r * 512 + k0 + c4 * 4);
            } else {
                float4 v = *reinterpret_cast<const float4*>(Aptr + (size_t)r * DIM + k0 + c4 * 4);
                p.x = packsplit(v.x); p.y = packsplit(v.y);
                p.z = packsplit(v.z); p.w = packsplit(v.w);
            }
            *reinterpret_cast<uint4*>(&As[r][c4 * 4]) = p;
        }
        // B tile(s) 32x64 -> packed hilo
        #pragma unroll
        for (int w = 0; w < NW; w++) {
            const float* Wb = w ? Wb1 : Wb0;
            #pragma unroll
            for (int j = 0; j < 2; j++) {
                int idx = tid + j * 256;
                int r = idx >> 4, c4 = idx & 15;
                float4 v = *reinterpret_cast<const float4*>(Wb + (size_t)(k0 + r) * ldw + c4 * 4);
                uint4 p;
                p.x = packsplit(v.x); p.y = packsplit(v.y);
                p.z = packsplit(v.z); p.w = packsplit(v.w);
                *reinterpret_cast<uint4*>(&Bs[w][r][c4 * 4]) = p;
            }
        }
        __syncthreads();

        #pragma unroll
        for (int kk = 0; kk < 2; kk++) {
            uint32_t ah[2][4], al[2][4];
            #pragma unroll
            for (int mt = 0; mt < 2; mt++) {
                int r0 = wm * 32 + mt * 16 + (lane >> 2);
                int c0 = kk * 16 + 2 * (lane & 3);
                uint2 w01 = *reinterpret_cast<const uint2*>(&As[r0][c0]);
                uint2 w23 = *reinterpret_cast<const uint2*>(&As[r0 + 8][c0]);
                uint2 w45 = *reinterpret_cast<const uint2*>(&As[r0][c0 + 8]);
                uint2 w67 = *reinterpret_cast<const uint2*>(&As[r0 + 8][c0 + 8]);
                ah[mt][0] = HI_PAIR(w01.x, w01.y); al[mt][0] = LO_PAIR(w01.x, w01.y);
                ah[mt][1] = HI_PAIR(w23.x, w23.y); al[mt][1] = LO_PAIR(w23.x, w23.y);
                ah[mt][2] = HI_PAIR(w45.x, w45.y); al[mt][2] = LO_PAIR(w45.x, w45.y);
                ah[mt][3] = HI_PAIR(w67.x, w67.y); al[mt][3] = LO_PAIR(w67.x, w67.y);
            }
            #pragma unroll
            for (int nt = 0; nt < 4; nt++) {
                int n = wn * 32 + nt * 8 + (lane >> 2);
                int r = kk * 16 + 2 * (lane & 3);
                #pragma unroll
                for (int w = 0; w < NW; w++) {
                    uint32_t v0 = Bs[w][r][n],     v1 = Bs[w][r + 1][n];
                    uint32_t v2 = Bs[w][r + 8][n], v3 = Bs[w][r + 9][n];
                    uint32_t bh[2], bl[2];
                    bh[0] = HI_PAIR(v0, v1); bl[0] = LO_PAIR(v0, v1);
                    bh[1] = HI_PAIR(v2, v3); bl[1] = LO_PAIR(v2, v3);
                    #pragma unroll
                    for (int mt = 0; mt < 2; mt++)
                        mma3(acc[w][mt][nt], ah[mt], al[mt], bh, bl);
                }
            }
        }
        __syncthreads();
    }

    // Epilogue
    #pragma unroll
    for (int mt = 0; mt < 2; mt++)
        #pragma unroll
        for (int nt = 0; nt < 4; nt++)
            #pragma unroll
            for (int i = 0; i < 4; i++) {
                int mloc = wm * 32 + mt * 16 + (lane >> 2) + ((i & 2) ? 8 : 0);
                int nloc = wn * 32 + nt * 8 + 2 * (lane & 3) + (i & 1);
                if (MODE == 0) {
                    size_t o = (((size_t)(bn * BATCH + bidx)) * QDIM + t0 + mloc) * HD + nloc;
                    g_Q[o] = packsplit(acc[0][mt][nt][i]);
                } else if (MODE == 1) {
                    size_t o = (((size_t)(bn * BATCH + bidx)) * GG + t0 + mloc) * HD + nloc;
                    g_K[o] = packsplit(acc[0][mt][nt][i]);
                    g_V[o] = packsplit(acc[1][mt][nt][i]);
                } else {
                    Outp[(size_t)(bm * 128 + mloc) * 512 + bn * 64 + nloc] = acc[0][mt][nt][i];
                }
            }
}

// ===========================================================================
// Flash attention (fp16 2-term): block = (128 q-rows) x (head,batch pair)
// 64-row KV chunks, 3-stage cp.async pipeline, 1 barrier per iteration.
// P C-frag pairs ARE k16 A-frag pairs -> no shuffles for the PV transpose.
// ===========================================================================
#define KLD 72
#define VLD 68
#define KS_U32 (64 * KLD)               // 4608
#define VS_U32 (64 * VLD)               // 4352
#define STAGE_U32 (KS_U32 + VS_U32)     // 8960
#define STAGE_BYTES (STAGE_U32 * 4)     // 35840
#define ATTN_SMEM (3 * STAGE_BYTES)     // 107520

__device__ __forceinline__ void prefetch_chunk(uint32_t sb, int st,
                                               const uint32_t* Kp, const uint32_t* Vp,
                                               int c, int tid)
{
    uint32_t kb = sb + st * STAGE_BYTES;
    uint32_t vb = kb + KS_U32 * 4;
    const uint32_t* kg = Kp + (size_t)c * 64 * 64;
    const uint32_t* vg = Vp + (size_t)c * 64 * 64;
    #pragma unroll
    for (int j = 0; j < 4; j++) {
        int idx = tid + j * 256;
        int row = idx >> 4, seg = idx & 15;
        cpa16(kb + row * (KLD * 4) + seg * 16, kg + row * 64 + seg * 4);
        cpa16(vb + row * (VLD * 4) + seg * 16, vg + row * 64 + seg * 4);
    }
}

__global__ __launch_bounds__(256)
void attn_kernel()
{
    extern __shared__ uint32_t dsm[];
    const uint32_t sb = (uint32_t)__cvta_generic_to_shared(dsm);

    const int tid  = threadIdx.x;
    const int lane = tid & 31;
    const int warp = tid >> 5;
    const int qt   = blockIdx.x;   // 0..3
    const int pair = blockIdx.y;   // 0..63 == h*8+b

    const uint32_t* Qp = g_Q + ((size_t)pair * QDIM + qt * 128 + warp * 16) * HD;
    const uint32_t* Kp = g_K + (size_t)pair * GG * HD;
    const uint32_t* Vp = g_V + (size_t)pair * GG * HD;

    const int r0 = lane >> 2;
    const int j2 = 2 * (lane & 3);

    // Q A-fragments (hi/lo) for all 4 k16-steps, loaded once
    uint32_t qh[4][4], ql[4][4];
    #pragma unroll
    for (int kk = 0; kk < 4; kk++) {
        int d0 = kk * 16 + j2;
        uint2 w01 = *reinterpret_cast<const uint2*>(Qp + (size_t)r0 * HD + d0);
        uint2 w23 = *reinterpret_cast<const uint2*>(Qp + (size_t)(r0 + 8) * HD + d0);
        uint2 w45 = *reinterpret_cast<const uint2*>(Qp + (size_t)r0 * HD + d0 + 8);
        uint2 w67 = *reinterpret_cast<const uint2*>(Qp + (size_t)(r0 + 8) * HD + d0 + 8);
        qh[kk][0] = HI_PAIR(w01.x, w01.y); ql[kk][0] = LO_PAIR(w01.x, w01.y);
        qh[kk][1] = HI_PAIR(w23.x, w23.y); ql[kk][1] = LO_PAIR(w23.x, w23.y);
        qh[kk][2] = HI_PAIR(w45.x, w45.y); ql[kk][2] = LO_PAIR(w45.x, w45.y);
        qh[kk][3] = HI_PAIR(w67.x, w67.y); ql[kk][3] = LO_PAIR(w67.x, w67.y);
    }

    float oacc[8][4];
    #pragma unroll
    for (int t = 0; t < 8; t++)
        #pragma unroll
        for (int i = 0; i < 4; i++) oacc[t][i] = 0.f;
    float m0 = -1e30f, m1 = -1e30f, l0 = 0.f, l1 = 0.f;

    // Pipeline prologue: chunks 0 and 1
    prefetch_chunk(sb, 0, Kp, Vp, 0, tid);
    asm volatile("cp.async.commit_group;");
    prefetch_chunk(sb, 1, Kp, Vp, 1, tid);
    asm volatile("cp.async.commit_group;");

    for (int c = 0; c < NCHUNK; c++) {
        asm volatile("cp.async.wait_group 1;");
        __syncthreads();
        if (c + 2 < NCHUNK)
            prefetch_chunk(sb, (c + 2) % 3, Kp, Vp, c + 2, tid);
        asm volatile("cp.async.commit_group;");

        const uint32_t* Ks = dsm + (c % 3) * STAGE_U32;
        const uint32_t* Vs = Ks + KS_U32;

        // S = Q @ K^T  (16 x 64 per warp)
        float sacc[8][4];
        #pragma unroll
        for (int t = 0; t < 8; t++)
            #pragma unroll
            for (int i = 0; i < 4; i++) sacc[t][i] = 0.f;

        #pragma unroll
        for (int kk = 0; kk < 4; kk++) {
            #pragma unroll
            for (int nt = 0; nt < 8; nt++) {
                int gcol = nt * 8 + r0;
                const uint32_t* p = Ks + gcol * KLD + kk * 16 + j2;
                uint2 w01 = *reinterpret_cast<const uint2*>(p);
                uint2 w23 = *reinterpret_cast<const uint2*>(p + 8);
                uint32_t bh[2], bl[2];
                bh[0] = HI_PAIR(w01.x, w01.y); bl[0] = LO_PAIR(w01.x, w01.y);
                bh[1] = HI_PAIR(w23.x, w23.y); bl[1] = LO_PAIR(w23.x, w23.y);
                mma3(sacc[nt], qh[kk], ql[kk], bh, bl);
            }
        }

        // Online softmax
        float mx0 = -1e30f, mx1 = -1e30f;
        #pragma unroll
        for (int t = 0; t < 8; t++) {
            sacc[t][0] *= NORM; sacc[t][1] *= NORM;
            sacc[t][2] *= NORM; sacc[t][3] *= NORM;
            mx0 = fmaxf(mx0, fmaxf(sacc[t][0], sacc[t][1]));
            mx1 = fmaxf(mx1, fmaxf(sacc[t][2], sacc[t][3]));
        }
        mx0 = fmaxf(mx0, __shfl_xor_sync(0xffffffffu, mx0, 1));
        mx0 = fmaxf(mx0, __shfl_xor_sync(0xffffffffu, mx0, 2));
        mx1 = fmaxf(mx1, __shfl_xor_sync(0xffffffffu, mx1, 1));
        mx1 = fmaxf(mx1, __shfl_xor_sync(0xffffffffu, mx1, 2));

        float mn0 = fmaxf(m0, mx0), mn1 = fmaxf(m1, mx1);
        float al0 = __expf(m0 - mn0), al1 = __expf(m1 - mn1);
        float s0 = 0.f, s1 = 0.f;
        #pragma unroll
        for (int t = 0; t < 8; t++) {
            sacc[t][0] = __expf(sacc[t][0] - mn0);
            sacc[t][1] = __expf(sacc[t][1] - mn0);
            sacc[t][2] = __expf(sacc[t][2] - mn1);
            sacc[t][3] = __expf(sacc[t][3] - mn1);
            s0 += sacc[t][0] + sacc[t][1];
            s1 += sacc[t][2] + sacc[t][3];
        }
        s0 += __shfl_xor_sync(0xffffffffu, s0, 1);
        s0 += __shfl_xor_sync(0xffffffffu, s0, 2);
        s1 += __shfl_xor_sync(0xffffffffu, s1, 1);
        s1 += __shfl_xor_sync(0xffffffffu, s1, 2);
        l0 = l0 * al0 + s0;
        l1 = l1 * al1 + s1;
        m0 = mn0; m1 = mn1;
        #pragma unroll
        for (int nt = 0; nt < 8; nt++) {
            oacc[nt][0] *= al0; oacc[nt][1] *= al0;
            oacc[nt][2] *= al1; oacc[nt][3] *= al1;
        }

        // O += P @ V : C-frag pairs are A-frag pairs (k16), no shuffles
        #pragma unroll
        for (int kk = 0; kk < 4; kk++) {
            uint32_t pah[4], pal[4];
            psplit2(sacc[2 * kk][0],     sacc[2 * kk][1],     pah[0], pal[0]);
            psplit2(sacc[2 * kk][2],     sacc[2 * kk][3],     pah[1], pal[1]);
            psplit2(sacc[2 * kk + 1][0], sacc[2 * kk + 1][1], pah[2], pal[2]);
            psplit2(sacc[2 * kk + 1][2], sacc[2 * kk + 1][3], pah[3], pal[3]);
            int gbase = kk * 16 + j2;
            #pragma unroll
            for (int nt = 0; nt < 8; nt++) {
                int dcol = nt * 8 + r0;
                uint32_t v0 = Vs[gbase * VLD + dcol];
                uint32_t v1 = Vs[(gbase + 1) * VLD + dcol];
                uint32_t v2 = Vs[(gbase + 8) * VLD + dcol];
                uint32_t v3 = Vs[(gbase + 9) * VLD + dcol];
                uint32_t bh[2], bl[2];
                bh[0] = HI_PAIR(v0, v1); bl[0] = LO_PAIR(v0, v1);
                bh[1] = HI_PAIR(v2, v3); bl[1] = LO_PAIR(v2, v3);
                mma3(oacc[nt], pah, pal, bh, bl);
            }
        }
    }

    // Normalize and write heads (packed) to (b, q, h*64+d)
    float inv0 = 1.f / l0, inv1 = 1.f / l1;
    int h = pair >> 3, b = pair & 7;
    #pragma unroll
    for (int nt = 0; nt < 8; nt++)
        #pragma unroll
        for (int i = 0; i < 4; i++) {
            int q = qt * 128 + warp * 16 + r0 + ((i & 2) ? 8 : 0);
            int d = nt * 8 + j2 + (i & 1);
            float v = oacc[nt][i] * ((i & 2) ? inv1 : inv0);
            g_Hd[((size_t)(b * QDIM + q)) * 512 + h * HD + d] = packsplit(v);
        }
}

extern "C" void kernel_launch(void* const* d_in, const int* in_sizes, int n_in,
                              void* d_out, int out_size)
{
    (void)in_sizes; (void)n_in; (void)out_size;
    const float* q  = (const float*)d_in[0];
    const float* Wq = (const float*)d_in[1];
    const float* Wk = (const float*)d_in[2];
    const float* Wv = (const float*)d_in[3];
    const float* Wo = (const float*)d_in[4];
    float* out = (float*)d_out;

    cudaFuncSetAttribute(attn_kernel, cudaFuncAttributeMaxDynamicSharedMemorySize, ATTN_SMEM);

    gemm_kernel<0><<<dim3(8, 32), 256>>>(q, Wq, nullptr, nullptr);       // Q proj
    gemm_kernel<1><<<dim3(8, 224), 256>>>(q, Wk, Wv, nullptr);           // K+V proj fused
    attn_kernel<<<dim3(4, 64), 256, ATTN_SMEM>>>();                      // flash attention
    gemm_kernel<2><<<dim3(8, 32), 256>>>(nullptr, Wo, nullptr, out);     // out proj
}